// round 11
// baseline (speedup 1.0000x reference)
#include <cuda_runtime.h>
#include <cuda_bf16.h>
#include <math_constants.h>
#include <cstdint>

#define BATCH 4
#define CH    256
#define HWN   4096
#define MASKN 1024

// ---------------- scratch ----------------
__device__ __nv_bfloat16 g_wn_hi[3][CH * CH];
__device__ __nv_bfloat16 g_wn_lo[3][CH * CH];
__device__ __nv_bfloat16 g_qT_hi[(size_t)BATCH * HWN * CH];
__device__ __nv_bfloat16 g_qT_lo[(size_t)BATCH * HWN * CH];
__device__ __nv_bfloat16 g_kT_hi[(size_t)BATCH * HWN * CH];
__device__ __nv_bfloat16 g_kT_lo[(size_t)BATCH * HWN * CH];
__device__ __nv_bfloat16 g_v_hi[(size_t)BATCH * CH * HWN];
__device__ __nv_bfloat16 g_v_lo[(size_t)BATCH * CH * HWN];
__device__ float g_sim[(size_t)BATCH * HWN * HWN];
__device__ __nv_bfloat16 g_att_hi[(size_t)BATCH * HWN * HWN];
__device__ __nv_bfloat16 g_att_lo[(size_t)BATCH * HWN * HWN];

// aT/bT scratch aliased into g_att_hi (dead until k_softmax writes it)
#define SPLIT_ELEMS ((size_t)BATCH * HWN * CH)   // 8 MiB each
__device__ __forceinline__ __nv_bfloat16* xT_ptr(int which, int part) {
    return g_att_hi + (size_t)(which * 2 + part) * SPLIT_ELEMS;
}

// ---------------- helpers ----------------
__device__ __forceinline__ uint32_t smem_u32(const void* p) {
    uint32_t a;
    asm("{ .reg .u64 t; cvta.to.shared.u64 t, %1; cvt.u32.u64 %0, t; }" : "=r"(a) : "l"(p));
    return a;
}
__device__ __forceinline__ void cp16(uint32_t dst, const void* src) {
    asm volatile("cp.async.cg.shared.global [%0], [%1], 16;" :: "r"(dst), "l"(src));
}
#define CP_COMMIT() asm volatile("cp.async.commit_group;")
#define CP_WAIT0()  asm volatile("cp.async.wait_group 0;")

__device__ __forceinline__ void ldsm_x4(uint32_t addr, uint32_t r[4]) {
    asm volatile("ldmatrix.sync.aligned.m8n8.x4.shared.b16 {%0,%1,%2,%3}, [%4];"
                 : "=r"(r[0]), "=r"(r[1]), "=r"(r[2]), "=r"(r[3]) : "r"(addr));
}
__device__ __forceinline__ void mma16816(float c[4], const uint32_t a[4], const uint32_t b[2]) {
    asm volatile("mma.sync.aligned.m16n8k16.row.col.f32.bf16.bf16.f32 "
                 "{%0,%1,%2,%3}, {%4,%5,%6,%7}, {%8,%9}, {%0,%1,%2,%3};"
                 : "+f"(c[0]), "+f"(c[1]), "+f"(c[2]), "+f"(c[3])
                 : "r"(a[0]), "r"(a[1]), "r"(a[2]), "r"(a[3]), "r"(b[0]), "r"(b[1]));
}

// tile rows x 32 bytes (16 bf16), swizzled so ldmatrix is conflict-free
__device__ __forceinline__ uint32_t swoff(int row, int seg) {
    return (uint32_t)row * 32 + ((seg ^ ((row >> 2) & 1)) << 4);
}

// CTA tile 128(M) x 256(N), k-chunk 16.
// stage layout: Ah[4KB] Al[4KB] Bh[8KB] Bl[8KB] = 24KB; 2 stages = 48KB
#define A_TILEB 4096
#define B_TILEB 8192
#define STAGEB  (2 * A_TILEB + 2 * B_TILEB)      // 24KB
struct MmaSmem { char buf[2][STAGEB]; };         // 48KB exactly

// A tile: 128 rows x 32B (256 threads, 1 cp16 each)
__device__ __forceinline__ void cp_tileA(uint32_t sdst, const __nv_bfloat16* g,
                                         size_t ld, int row0, int k0) {
    const int t = threadIdx.x;
    const int row = t >> 1;
    const int seg = t & 1;
    const char* src = reinterpret_cast<const char*>(g + (size_t)(row0 + row) * ld + k0 + seg * 8);
    cp16(sdst + swoff(row, seg), src);
}
// B tile: 256 rows x 32B (256 threads, 2 cp16 each)
__device__ __forceinline__ void cp_tileB(uint32_t sdst, const __nv_bfloat16* g,
                                         size_t ld, int row0, int k0) {
    const int row = threadIdx.x;
    const char* src = reinterpret_cast<const char*>(g + (size_t)(row0 + row) * ld + k0);
    cp16(sdst + swoff(row, 0), src);
    cp16(sdst + swoff(row, 1), src + 16);
}

__device__ __forceinline__ void load_stage16(uint32_t sb,
    const __nv_bfloat16* Ah, const __nv_bfloat16* Al, size_t lda, int m0,
    const __nv_bfloat16* Bh, const __nv_bfloat16* Bl, size_t ldb, int n0, int k0)
{
    cp_tileA(sb,                         Ah, lda, m0, k0);
    cp_tileA(sb + A_TILEB,               Al, lda, m0, k0);
    cp_tileB(sb + 2 * A_TILEB,           Bh, ldb, n0, k0);
    cp_tileB(sb + 2 * A_TILEB + B_TILEB, Bl, ldb, n0, k0);
}

// one k=16 slice: acc += Ah*Bh + Ah*Bl + Al*Bh   (warp tile 64x64)
__device__ __forceinline__ void compute_stage16(uint32_t sb, float acc[4][8][4],
                                                int lane, int wm, int wn)
{
    const uint32_t sAh = sb, sAl = sb + A_TILEB;
    const uint32_t sBh = sb + 2 * A_TILEB, sBl = sb + 2 * A_TILEB + B_TILEB;
    uint32_t ah[4][4], al[4][4];
    const int aseg = lane >> 4;
#pragma unroll
    for (int mt = 0; mt < 4; ++mt) {
        const int arow = wm * 64 + mt * 16 + (lane & 15);
        ldsm_x4(sAh + swoff(arow, aseg), ah[mt]);
        ldsm_x4(sAl + swoff(arow, aseg), al[mt]);
    }
    const int brow_in = ((lane >> 4) << 3) + (lane & 7);
    const int bseg = (lane >> 3) & 1;
#pragma unroll
    for (int ntp = 0; ntp < 4; ++ntp) {
        const int brow = wn * 64 + ntp * 16 + brow_in;
        uint32_t bh[4], bl[4];
        ldsm_x4(sBh + swoff(brow, bseg), bh);
        ldsm_x4(sBl + swoff(brow, bseg), bl);
#pragma unroll
        for (int mt = 0; mt < 4; ++mt)
#pragma unroll
            for (int h = 0; h < 2; ++h)
                mma16816(acc[mt][ntp * 2 + h], ah[mt], bh + h * 2);
#pragma unroll
        for (int mt = 0; mt < 4; ++mt)
#pragma unroll
            for (int h = 0; h < 2; ++h)
                mma16816(acc[mt][ntp * 2 + h], ah[mt], bl + h * 2);
#pragma unroll
        for (int mt = 0; mt < 4; ++mt)
#pragma unroll
            for (int h = 0; h < 2; ++h)
                mma16816(acc[mt][ntp * 2 + h], al[mt], bh + h * 2);
    }
}

// C[128x256] = A[m0..+128, :k] * B[n0..+256, :k]^T (both [row][k], 3-term hi/lo)
// 2-stage double buffer, one barrier per chunk
__device__ __forceinline__ void gemm_hilo(uint32_t sb0,
    const __nv_bfloat16* Ah, const __nv_bfloat16* Al, size_t lda, int m0,
    const __nv_bfloat16* Bh, const __nv_bfloat16* Bl, size_t ldb, int n0,
    int kTotal, float acc[4][8][4])
{
    const int lane = threadIdx.x & 31;
    const int w = threadIdx.x >> 5;
    const int wm = w & 1, wn = w >> 1;
    const int nk = kTotal / 16;

    load_stage16(sb0, Ah, Al, lda, m0, Bh, Bl, ldb, n0, 0);
    CP_COMMIT();
    for (int s = 0; s < nk; ++s) {
        CP_WAIT0();
        __syncthreads();   // stage-s data visible, all warps done with stage s-1 buffer
        if (s + 1 < nk) {
            load_stage16(sb0 + ((s + 1) & 1) * STAGEB,
                         Ah, Al, lda, m0, Bh, Bl, ldb, n0, (s + 1) * 16);
            CP_COMMIT();
        }
        compute_stage16(sb0 + (s & 1) * STAGEB, acc, lane, wm, wn);
    }
}

__device__ __forceinline__ void split_hilo(float v, __nv_bfloat16& h, __nv_bfloat16& l) {
    h = __float2bfloat16_rn(v);
    l = __float2bfloat16_rn(v - __bfloat162float(h));
}

// ---------------- kernel 0: weight standardization (all 3 convs, one launch) ----------------
__global__ __launch_bounds__(256) void k_ws(const float* __restrict__ wq,
                                            const float* __restrict__ gq,
                                            const float* __restrict__ wk,
                                            const float* __restrict__ gk,
                                            const float* __restrict__ wv,
                                            const float* __restrict__ gv)
{
    const int which = blockIdx.y;
    const float* __restrict__ w    = (which == 0) ? wq : (which == 1) ? wk : wv;
    const float* __restrict__ gain = (which == 0) ? gq : (which == 1) ? gk : gv;

    const int o = blockIdx.x;
    const int t = threadIdx.x;
    const float v = w[o * CH + t];
    float s = v, ss = v * v;
#pragma unroll
    for (int off = 16; off; off >>= 1) {
        s  += __shfl_xor_sync(0xFFFFFFFFu, s,  off);
        ss += __shfl_xor_sync(0xFFFFFFFFu, ss, off);
    }
    __shared__ float sh_s[8], sh_ss[8], sh_scale, sh_msc;
    if ((t & 31) == 0) { sh_s[t >> 5] = s; sh_ss[t >> 5] = ss; }
    __syncthreads();
    if (t == 0) {
        float S = 0.f, SS = 0.f;
#pragma unroll
        for (int k = 0; k < 8; ++k) { S += sh_s[k]; SS += sh_ss[k]; }
        float mean = S * (1.0f / CH);
        float var  = (SS - (float)CH * mean * mean) * (1.0f / (CH - 1));
        float scale = rsqrtf(fmaxf(var * (float)CH, 1e-4f)) * gain[o];
        sh_scale = scale;
        sh_msc   = mean * scale;
    }
    __syncthreads();
    const float wn = v * sh_scale - sh_msc;
    __nv_bfloat16 h, l;
    split_hilo(wn, h, l);
    g_wn_hi[which][o * CH + t] = h;
    g_wn_lo[which][o * CH + t] = l;
}

// ---------------- kernel 1: transpose+split both a and b ----------------
__global__ __launch_bounds__(256) void k_split(const float* __restrict__ aIn,
                                               const float* __restrict__ bIn)
{
    __shared__ float t[64][65];
    const int which = blockIdx.z >> 2;
    const int batch = blockIdx.z & 3;
    const int hw0 = blockIdx.x * 64;
    const int c0  = blockIdx.y * 64;
    const float* __restrict__ src = (which ? bIn : aIn) + (size_t)batch * CH * HWN;
    const int tid = threadIdx.x;

    const int lr = tid >> 6;
    const int lc = tid & 63;
#pragma unroll
    for (int i = 0; i < 16; ++i) {
        const int r = i * 4 + lr;
        t[r][lc] = src[(size_t)(c0 + r) * HWN + hw0 + lc];
    }
    __syncthreads();

    __nv_bfloat16* __restrict__ H = xT_ptr(which, 0) + (size_t)batch * HWN * CH;
    __nv_bfloat16* __restrict__ L = xT_ptr(which, 1) + (size_t)batch * HWN * CH;
    const int wr = tid >> 5;
    const int wc = (tid & 31) * 2;
#pragma unroll
    for (int i = 0; i < 8; ++i) {
        const int r = i * 8 + wr;
        float v0 = t[wc][r], v1 = t[wc + 1][r];
        __nv_bfloat16 h0, l0, h1, l1;
        split_hilo(v0, h0, l0);
        split_hilo(v1, h1, l1);
        const size_t o = (size_t)(hw0 + r) * CH + c0 + wc;
        *reinterpret_cast<__nv_bfloat162*>(&H[o]) = __nv_bfloat162(h0, h1);
        *reinterpret_cast<__nv_bfloat162*>(&L[o]) = __nv_bfloat162(l0, l1);
    }
}

// ---------------- kernel 2: v = wn @ aT^T (mma), out [c][hw] hi/lo ----------------
__global__ __launch_bounds__(256, 1) void k_v_mma(const float* __restrict__ bv)
{
    __shared__ __align__(1024) MmaSmem sm;
    const uint32_t sb0 = smem_u32(&sm);

    const int batch = blockIdx.z;
    const size_t xoff = (size_t)batch * HWN * CH;
    const size_t voff = (size_t)batch * CH * HWN;

    const int m0 = blockIdx.y * 128;   // c
    const int n0 = blockIdx.x * 256;   // hw

    float acc[4][8][4] = {};
    gemm_hilo(sb0, g_wn_hi[2], g_wn_lo[2], CH, m0,
              xT_ptr(0, 0) + xoff, xT_ptr(0, 1) + xoff, CH, n0, CH, acc);

    const int lane = threadIdx.x & 31;
    const int w = threadIdx.x >> 5;
    const int wm = w & 1, wn = w >> 1;
    const int gm_base = m0 + wm * 64 + (lane >> 2);
    const int gn_base = n0 + wn * 64 + (lane & 3) * 2;
#pragma unroll
    for (int mt = 0; mt < 4; ++mt) {
#pragma unroll
        for (int nt = 0; nt < 8; ++nt) {
            const int gn = gn_base + nt * 8;
#pragma unroll
            for (int half = 0; half < 2; ++half) {
                const int gm = gm_base + mt * 16 + half * 8;
                const float bb = bv[gm];
                float v0 = acc[mt][nt][half * 2 + 0] + bb;
                float v1 = acc[mt][nt][half * 2 + 1] + bb;
                __nv_bfloat16 h0, l0, h1, l1;
                split_hilo(v0, h0, l0);
                split_hilo(v1, h1, l1);
                const size_t o = voff + (size_t)gm * HWN + gn;
                *reinterpret_cast<__nv_bfloat162*>(&g_v_hi[o]) = __nv_bfloat162(h0, h1);
                *reinterpret_cast<__nv_bfloat162*>(&g_v_lo[o]) = __nv_bfloat162(l0, l1);
            }
        }
    }
}

// ---------------- kernel 3: qT/kT = xT @ wn^T (mma), out [hw][c] hi/lo ----------------
__global__ __launch_bounds__(256, 1) void k_qk_mma(const float* __restrict__ bq,
                                                   const float* __restrict__ bk)
{
    __shared__ __align__(1024) MmaSmem sm;
    const uint32_t sb0 = smem_u32(&sm);

    const int which = blockIdx.z >> 2;
    const int batch = blockIdx.z & 3;
    const size_t xoff = (size_t)batch * HWN * CH;
    const __nv_bfloat16* Xh = xT_ptr(which, 0) + xoff;
    const __nv_bfloat16* Xl = xT_ptr(which, 1) + xoff;
    const __nv_bfloat16* Wh = g_wn_hi[which];
    const __nv_bfloat16* Wl = g_wn_lo[which];
    const float* __restrict__ bias = which ? bk : bq;
    __nv_bfloat16* __restrict__ Hi = (which ? g_kT_hi : g_qT_hi) + xoff;
    __nv_bfloat16* __restrict__ Lo = (which ? g_kT_lo : g_qT_lo) + xoff;

    const int m0 = blockIdx.y * 128;   // hw
    const int n0 = 0;                  // co covers full 256

    float acc[4][8][4] = {};
    gemm_hilo(sb0, Xh, Xl, CH, m0, Wh, Wl, CH, n0, CH, acc);

    const int lane = threadIdx.x & 31;
    const int w = threadIdx.x >> 5;
    const int wm = w & 1, wn = w >> 1;
    const int gm_base = m0 + wm * 64 + (lane >> 2);
    const int gn_base = n0 + wn * 64 + (lane & 3) * 2;
#pragma unroll
    for (int mt = 0; mt < 4; ++mt) {
#pragma unroll
        for (int nt = 0; nt < 8; ++nt) {
            const int gn = gn_base + nt * 8;
            const float b0 = bias[gn], b1 = bias[gn + 1];
#pragma unroll
            for (int half = 0; half < 2; ++half) {
                const int gm = gm_base + mt * 16 + half * 8;
                float v0 = acc[mt][nt][half * 2 + 0] + b0;
                float v1 = acc[mt][nt][half * 2 + 1] + b1;
                __nv_bfloat16 h0, l0, h1, l1;
                split_hilo(v0, h0, l0);
                split_hilo(v1, h1, l1);
                const size_t o = (size_t)gm * CH + gn;
                *reinterpret_cast<__nv_bfloat162*>(&Hi[o]) = __nv_bfloat162(h0, h1);
                *reinterpret_cast<__nv_bfloat162*>(&Lo[o]) = __nv_bfloat162(l0, l1);
            }
        }
    }
}

// ---------------- kernel 4: sim = qT @ kT^T (mma.sync) ----------------
__global__ __launch_bounds__(256, 1) void k_sim_mma()
{
    __shared__ __align__(1024) MmaSmem sm;
    const uint32_t sb0 = smem_u32(&sm);

    const int batch = blockIdx.z;
    const int m0 = blockIdx.y * 128;
    const int n0 = blockIdx.x * 256;
    const size_t boff = (size_t)batch * HWN * CH;

    float acc[4][8][4] = {};
    gemm_hilo(sb0, g_qT_hi + boff, g_qT_lo + boff, CH, m0,
              g_kT_hi + boff, g_kT_lo + boff, CH, n0, CH, acc);

    float* __restrict__ S = g_sim + (size_t)batch * HWN * HWN;
    const int lane = threadIdx.x & 31;
    const int w = threadIdx.x >> 5;
    const int wm = w & 1, wn = w >> 1;
    const int gm_base = m0 + wm * 64 + (lane >> 2);
    const int gn_base = n0 + wn * 64 + (lane & 3) * 2;
#pragma unroll
    for (int mt = 0; mt < 4; ++mt) {
#pragma unroll
        for (int nt = 0; nt < 8; ++nt) {
            const int gm = gm_base + mt * 16;
            const int gn = gn_base + nt * 8;
            float2 p0 = {acc[mt][nt][0], acc[mt][nt][1]};
            float2 p1 = {acc[mt][nt][2], acc[mt][nt][3]};
            *reinterpret_cast<float2*>(&S[(size_t)gm * HWN + gn]) = p0;
            *reinterpret_cast<float2*>(&S[(size_t)(gm + 8) * HWN + gn]) = p1;
        }
    }
}

// ---------------- kernel 5: masked softmax -> att bf16 hi/lo ----------------
__global__ __launch_bounds__(256) void k_softmax(const float* __restrict__ cIn)
{
    const int i = blockIdx.x;
    const int batch = blockIdx.y;
    const float* __restrict__ row = g_sim + ((size_t)batch * HWN + i) * HWN;
    __nv_bfloat16* __restrict__ Hi = g_att_hi + ((size_t)batch * HWN + i) * HWN;
    __nv_bfloat16* __restrict__ Lo = g_att_lo + ((size_t)batch * HWN + i) * HWN;

    const int h = i >> 6, w = i & 63;
    const float m = cIn[batch * MASKN + (h >> 1) * 32 + (w >> 1)];

    const int tid = threadIdx.x;
    float x[16];
    float vmax = -CUDART_INF_F;
#pragma unroll
    for (int p = 0; p < 4; ++p) {
        float4 v = *reinterpret_cast<const float4*>(&row[(p * 256 + tid) * 4]);
        x[p * 4 + 0] = m * v.x; x[p * 4 + 1] = m * v.y;
        x[p * 4 + 2] = m * v.z; x[p * 4 + 3] = m * v.w;
#pragma unroll
        for (int q = 0; q < 4; ++q) vmax = fmaxf(vmax, x[p * 4 + q]);
    }

    __shared__ float redm[8], reds[8], sh_max, sh_sum;
#pragma unroll
    for (int off = 16; off; off >>= 1) vmax = fmaxf(vmax, __shfl_xor_sync(0xFFFFFFFFu, vmax, off));
    if ((tid & 31) == 0) redm[tid >> 5] = vmax;
    __syncthreads();
    if (tid == 0) {
        float v = redm[0];
#pragma unroll
        for (int k = 1; k < 8; ++k) v = fmaxf(v, redm[k]);
        sh_max = v;
    }
    __syncthreads();
    const float M = sh_max;

    float total = 0.f;
#pragma unroll
    for (int q = 0; q < 16; ++q) {
        float e = __expf(x[q] - M);
        x[q] = e;
        total += e;
    }
#pragma unroll
    for (int off = 16; off; off >>= 1) total += __shfl_xor_sync(0xFFFFFFFFu, total, off);
    if ((tid & 31) == 0) reds[tid >> 5] = total;
    __syncthreads();
    if (tid == 0) {
        float v = 0.f;
#pragma unroll
        for (int k = 0; k < 8; ++k) v += reds[k];
        sh_sum = v;
    }
    __syncthreads();
    const float inv = 1.0f / sh_sum;

#pragma unroll
    for (int p = 0; p < 4; ++p) {
        const int idx = (p * 256 + tid) * 4;
#pragma unroll
        for (int q = 0; q < 4; q += 2) {
            float v0 = x[p * 4 + q] * inv;
            float v1 = x[p * 4 + q + 1] * inv;
            __nv_bfloat16 h0, l0, h1, l1;
            split_hilo(v0, h0, l0);
            split_hilo(v1, h1, l1);
            *reinterpret_cast<__nv_bfloat162*>(&Hi[idx + q]) = __nv_bfloat162(h0, h1);
            *reinterpret_cast<__nv_bfloat162*>(&Lo[idx + q]) = __nv_bfloat162(l0, l1);
        }
    }
}

// ---------------- kernel 6: out = v @ att^T (mma.sync), fused blend ----------------
__global__ __launch_bounds__(256, 1) void k_pv_mma(const float* __restrict__ aIn,
                                                   const float* __restrict__ cIn,
                                                   const float* __restrict__ gammaPtr,
                                                   float* __restrict__ out)
{
    __shared__ __align__(1024) MmaSmem sm;
    const uint32_t sb0 = smem_u32(&sm);

    const int batch = blockIdx.z;
    const int m0 = blockIdx.y * 128;   // channel
    const int n0 = blockIdx.x * 256;   // position i
    const size_t voff = (size_t)batch * CH * HWN;
    const size_t aoff = (size_t)batch * HWN * HWN;

    float acc[4][8][4] = {};
    gemm_hilo(sb0, g_v_hi + voff, g_v_lo + voff, HWN, m0,
              g_att_hi + aoff, g_att_lo + aoff, HWN, n0, HWN, acc);

    const float gamma = gammaPtr[0];
    const int lane = threadIdx.x & 31;
    const int w = threadIdx.x >> 5;
    const int wm = w & 1, wn = w >> 1;
    const int gm_base = m0 + wm * 64 + (lane >> 2);
    const int gn_base = n0 + wn * 64 + (lane & 3) * 2;

#pragma unroll
    for (int mt = 0; mt < 4; ++mt) {
#pragma unroll
        for (int nt = 0; nt < 8; ++nt) {
            const int gi = gn_base + nt * 8;
            const int hh = gi >> 6, ww = gi & 63;
            const float cr = cIn[batch * MASKN + (hh >> 1) * 32 + (ww >> 1)];
            const float gb = gamma * (1.0f - cr);
#pragma unroll
            for (int half = 0; half < 2; ++half) {
                const int gm = gm_base + mt * 16 + half * 8;
                const size_t base = ((size_t)batch * CH + gm) * HWN + gi;
                float2 av = *reinterpret_cast<const float2*>(&aIn[base]);
                float2 o;
                o.x = av.x * cr + gb * acc[mt][nt][half * 2 + 0];
                o.y = av.y * cr + gb * acc[mt][nt][half * 2 + 1];
                *reinterpret_cast<float2*>(&out[base]) = o;
            }
        }
    }
}

// ---------------- launch ----------------
extern "C" void kernel_launch(void* const* d_in, const int* in_sizes, int n_in,
                              void* d_out, int out_size)
{
    const float* a     = (const float*)d_in[0];
    const float* b     = (const float*)d_in[1];
    const float* cmask = (const float*)d_in[2];
    const float* wq    = (const float*)d_in[3];
    const float* bq    = (const float*)d_in[4];
    const float* gq    = (const float*)d_in[5];
    const float* wk    = (const float*)d_in[6];
    const float* bk    = (const float*)d_in[7];
    const float* gk    = (const float*)d_in[8];
    const float* wv    = (const float*)d_in[9];
    const float* bv    = (const float*)d_in[10];
    const float* gv    = (const float*)d_in[11];
    const float* gamma = (const float*)d_in[12];
    float* out = (float*)d_out;

    k_ws<<<dim3(CH, 3), 256>>>(wq, gq, wk, gk, wv, gv);

    dim3 gsp(HWN / 64, CH / 64, 8);
    k_split<<<gsp, 256>>>(a, b);

    dim3 gvv(HWN / 256, CH / 128, BATCH);      // 16 x 2 x 4
    k_v_mma<<<gvv, 256>>>(bv);

    dim3 gqk(1, HWN / 128, 8);                 // 1 x 32 x 8
    k_qk_mma<<<gqk, 256>>>(bq, bk);

    dim3 gsim(HWN / 256, HWN / 128, BATCH);    // 16 x 32 x 4
    k_sim_mma<<<gsim, 256>>>();

    k_softmax<<<dim3(HWN, BATCH), 256>>>(cmask);

    dim3 gpv(HWN / 256, CH / 128, BATCH);      // 16 x 2 x 4
    k_pv_mma<<<gpv, 256>>>(a, cmask, gamma, out);
}

// round 12
// speedup vs baseline: 1.0145x; 1.0145x over previous
#include <cuda_runtime.h>
#include <cuda_bf16.h>
#include <math_constants.h>
#include <cstdint>

#define BATCH 4
#define CH    256
#define HWN   4096
#define MASKN 1024

// ---------------- scratch ----------------
__device__ __nv_bfloat16 g_wn_hi[3][CH * CH];
__device__ __nv_bfloat16 g_wn_lo[3][CH * CH];
__device__ __nv_bfloat16 g_qT_hi[(size_t)BATCH * HWN * CH];
__device__ __nv_bfloat16 g_qT_lo[(size_t)BATCH * HWN * CH];
__device__ __nv_bfloat16 g_kT_hi[(size_t)BATCH * HWN * CH];
__device__ __nv_bfloat16 g_kT_lo[(size_t)BATCH * HWN * CH];
__device__ __nv_bfloat16 g_v_hi[(size_t)BATCH * CH * HWN];
__device__ __nv_bfloat16 g_v_lo[(size_t)BATCH * CH * HWN];
__device__ float g_sim[(size_t)BATCH * HWN * HWN];
__device__ __nv_bfloat16 g_att_hi[(size_t)BATCH * HWN * HWN];
__device__ __nv_bfloat16 g_att_lo[(size_t)BATCH * HWN * HWN];

// aT/bT scratch aliased into g_att_hi (dead until k_softmax writes it;
// all aT/bT consumers run before k_softmax in the serial stream).
#define SPLIT_ELEMS ((size_t)BATCH * HWN * CH)   // 8 MiB each
__device__ __forceinline__ __nv_bfloat16* xT_ptr(int which, int part) {
    return g_att_hi + (size_t)(which * 2 + part) * SPLIT_ELEMS;
}

// ---------------- helpers ----------------
__device__ __forceinline__ uint32_t smem_u32(const void* p) {
    uint32_t a;
    asm("{ .reg .u64 t; cvta.to.shared.u64 t, %1; cvt.u32.u64 %0, t; }" : "=r"(a) : "l"(p));
    return a;
}
__device__ __forceinline__ void cp16(uint32_t dst, const void* src) {
    asm volatile("cp.async.cg.shared.global [%0], [%1], 16;" :: "r"(dst), "l"(src));
}
#define CP_COMMIT() asm volatile("cp.async.commit_group;")
#define CP_WAIT1()  asm volatile("cp.async.wait_group 1;")
#define CP_WAIT0()  asm volatile("cp.async.wait_group 0;")

__device__ __forceinline__ void ldsm_x4(uint32_t addr, uint32_t r[4]) {
    asm volatile("ldmatrix.sync.aligned.m8n8.x4.shared.b16 {%0,%1,%2,%3}, [%4];"
                 : "=r"(r[0]), "=r"(r[1]), "=r"(r[2]), "=r"(r[3]) : "r"(addr));
}
__device__ __forceinline__ void mma16816(float c[4], const uint32_t a[4], const uint32_t b[2]) {
    asm volatile("mma.sync.aligned.m16n8k16.row.col.f32.bf16.bf16.f32 "
                 "{%0,%1,%2,%3}, {%4,%5,%6,%7}, {%8,%9}, {%0,%1,%2,%3};"
                 : "+f"(c[0]), "+f"(c[1]), "+f"(c[2]), "+f"(c[3])
                 : "r"(a[0]), "r"(a[1]), "r"(a[2]), "r"(a[3]), "r"(b[0]), "r"(b[1]));
}

// tile layout: 128 rows x 32 bytes (16 bf16), swizzled so ldmatrix is conflict-free
__device__ __forceinline__ uint32_t swoff(int row, int seg) {
    return (uint32_t)row * 32 + ((seg ^ ((row >> 2) & 1)) << 4);
}

#define TILE16B 4096                     // 128 x 32B
#define STAGEB  (4 * TILE16B)            // 16KB per stage (Ah,Al,Bh,Bl)
// 3 stages = 48KB exactly (static smem ceiling)
struct MmaSmem { char buf[3][4][TILE16B]; };

__device__ __forceinline__ void cp_tile16(uint32_t sdst, const __nv_bfloat16* g,
                                          size_t ld, int row0, int k0) {
    const int t = threadIdx.x;
    const int row = t >> 1;
    const int seg = t & 1;
    const char* src = reinterpret_cast<const char*>(g + (size_t)(row0 + row) * ld + k0 + seg * 8);
    cp16(sdst + swoff(row, seg), src);
}

__device__ __forceinline__ void load_stage16(uint32_t sb,
    const __nv_bfloat16* Ah, const __nv_bfloat16* Al, size_t lda, int m0,
    const __nv_bfloat16* Bh, const __nv_bfloat16* Bl, size_t ldb, int n0, int k0)
{
    cp_tile16(sb,               Ah, lda, m0, k0);
    cp_tile16(sb + TILE16B,     Al, lda, m0, k0);
    cp_tile16(sb + 2 * TILE16B, Bh, ldb, n0, k0);
    cp_tile16(sb + 3 * TILE16B, Bl, ldb, n0, k0);
}

// one k=16 slice: acc += Ah*Bh + Ah*Bl + Al*Bh   (warp tile 32x64), term-major
__device__ __forceinline__ void compute_stage16(uint32_t sb, float acc[2][8][4],
                                                int lane, int wm, int wn)
{
    const uint32_t sAh = sb, sAl = sb + TILE16B, sBh = sb + 2 * TILE16B, sBl = sb + 3 * TILE16B;
    uint32_t ah[2][4], al[2][4];
    const int aseg = lane >> 4;
#pragma unroll
    for (int mt = 0; mt < 2; ++mt) {
        const int arow = wm * 32 + mt * 16 + (lane & 15);
        ldsm_x4(sAh + swoff(arow, aseg), ah[mt]);
        ldsm_x4(sAl + swoff(arow, aseg), al[mt]);
    }
    const int brow_in = ((lane >> 4) << 3) + (lane & 7);
    const int bseg = (lane >> 3) & 1;
#pragma unroll
    for (int ntp = 0; ntp < 4; ++ntp) {
        const int brow = wn * 64 + ntp * 16 + brow_in;
        uint32_t bh[4], bl[4];
        ldsm_x4(sBh + swoff(brow, bseg), bh);
        ldsm_x4(sBl + swoff(brow, bseg), bl);
#pragma unroll
        for (int mt = 0; mt < 2; ++mt)
#pragma unroll
            for (int h = 0; h < 2; ++h)
                mma16816(acc[mt][ntp * 2 + h], ah[mt], bh + h * 2);
#pragma unroll
        for (int mt = 0; mt < 2; ++mt)
#pragma unroll
            for (int h = 0; h < 2; ++h)
                mma16816(acc[mt][ntp * 2 + h], ah[mt], bl + h * 2);
#pragma unroll
        for (int mt = 0; mt < 2; ++mt)
#pragma unroll
            for (int h = 0; h < 2; ++h)
                mma16816(acc[mt][ntp * 2 + h], al[mt], bh + h * 2);
    }
}

// one pipeline step: wait for stage s, prefetch stage s+2 into pbase, compute stage s
__device__ __forceinline__ void pipe_step(int s, int nk, uint32_t cbase, uint32_t pbase,
    const __nv_bfloat16* Ah, const __nv_bfloat16* Al, size_t lda, int m0,
    const __nv_bfloat16* Bh, const __nv_bfloat16* Bl, size_t ldb, int n0,
    float acc[2][8][4], int lane, int wm, int wn)
{
    if (s >= nk) return;
    if (s + 1 < nk) CP_WAIT1(); else CP_WAIT0();
    __syncthreads();   // stage-s data visible AND all warps done computing stage s-1
    if (s + 2 < nk) {
        load_stage16(pbase, Ah, Al, lda, m0, Bh, Bl, ldb, n0, (s + 2) * 16);
        CP_COMMIT();
    }
    compute_stage16(cbase, acc, lane, wm, wn);
}

// C[128x128] = A[m0..+128, :k] * B[n0..+128, :k]^T (both [row][k], 3-term hi/lo)
// 3-stage pipeline, compile-time buffer indices, one barrier per chunk
__device__ __forceinline__ void gemm_hilo(uint32_t sb0,
    const __nv_bfloat16* Ah, const __nv_bfloat16* Al, size_t lda, int m0,
    const __nv_bfloat16* Bh, const __nv_bfloat16* Bl, size_t ldb, int n0,
    int kTotal, float acc[2][8][4])
{
    const int lane = threadIdx.x & 31;
    const int w = threadIdx.x >> 5;
    const int wm = w & 3, wn = w >> 2;
    const int nk = kTotal / 16;
    const uint32_t b0 = sb0, b1 = sb0 + STAGEB, b2 = sb0 + 2 * STAGEB;

    load_stage16(b0, Ah, Al, lda, m0, Bh, Bl, ldb, n0, 0);
    CP_COMMIT();
    if (nk > 1) {
        load_stage16(b1, Ah, Al, lda, m0, Bh, Bl, ldb, n0, 16);
        CP_COMMIT();
    }
    for (int s0 = 0; s0 < nk; s0 += 3) {
        pipe_step(s0 + 0, nk, b0, b2, Ah, Al, lda, m0, Bh, Bl, ldb, n0, acc, lane, wm, wn);
        pipe_step(s0 + 1, nk, b1, b0, Ah, Al, lda, m0, Bh, Bl, ldb, n0, acc, lane, wm, wn);
        pipe_step(s0 + 2, nk, b2, b1, Ah, Al, lda, m0, Bh, Bl, ldb, n0, acc, lane, wm, wn);
    }
}

__device__ __forceinline__ void split_hilo(float v, __nv_bfloat16& h, __nv_bfloat16& l) {
    h = __float2bfloat16_rn(v);
    l = __float2bfloat16_rn(v - __bfloat162float(h));
}

// ---------------- kernel 0: weight standardization (all 3 convs, one launch) ----------------
__global__ __launch_bounds__(256) void k_ws(const float* __restrict__ wq,
                                            const float* __restrict__ gq,
                                            const float* __restrict__ wk,
                                            const float* __restrict__ gk,
                                            const float* __restrict__ wv,
                                            const float* __restrict__ gv)
{
    const int which = blockIdx.y;
    const float* __restrict__ w    = (which == 0) ? wq : (which == 1) ? wk : wv;
    const float* __restrict__ gain = (which == 0) ? gq : (which == 1) ? gk : gv;

    const int o = blockIdx.x;
    const int t = threadIdx.x;
    const float v = w[o * CH + t];
    float s = v, ss = v * v;
#pragma unroll
    for (int off = 16; off; off >>= 1) {
        s  += __shfl_xor_sync(0xFFFFFFFFu, s,  off);
        ss += __shfl_xor_sync(0xFFFFFFFFu, ss, off);
    }
    __shared__ float sh_s[8], sh_ss[8], sh_scale, sh_msc;
    if ((t & 31) == 0) { sh_s[t >> 5] = s; sh_ss[t >> 5] = ss; }
    __syncthreads();
    if (t == 0) {
        float S = 0.f, SS = 0.f;
#pragma unroll
        for (int k = 0; k < 8; ++k) { S += sh_s[k]; SS += sh_ss[k]; }
        float mean = S * (1.0f / CH);
        float var  = (SS - (float)CH * mean * mean) * (1.0f / (CH - 1));
        float scale = rsqrtf(fmaxf(var * (float)CH, 1e-4f)) * gain[o];
        sh_scale = scale;
        sh_msc   = mean * scale;
    }
    __syncthreads();
    const float wn = v * sh_scale - sh_msc;
    __nv_bfloat16 h, l;
    split_hilo(wn, h, l);
    g_wn_hi[which][o * CH + t] = h;
    g_wn_lo[which][o * CH + t] = l;
}

// ---------------- kernel 1: transpose+split both a and b ----------------
__global__ __launch_bounds__(256) void k_split(const float* __restrict__ aIn,
                                               const float* __restrict__ bIn)
{
    __shared__ float t[64][65];
    const int which = blockIdx.z >> 2;
    const int batch = blockIdx.z & 3;
    const int hw0 = blockIdx.x * 64;
    const int c0  = blockIdx.y * 64;
    const float* __restrict__ src = (which ? bIn : aIn) + (size_t)batch * CH * HWN;
    const int tid = threadIdx.x;

    const int lr = tid >> 6;
    const int lc = tid & 63;
#pragma unroll
    for (int i = 0; i < 16; ++i) {
        const int r = i * 4 + lr;
        t[r][lc] = src[(size_t)(c0 + r) * HWN + hw0 + lc];
    }
    __syncthreads();

    __nv_bfloat16* __restrict__ H = xT_ptr(which, 0) + (size_t)batch * HWN * CH;
    __nv_bfloat16* __restrict__ L = xT_ptr(which, 1) + (size_t)batch * HWN * CH;
    const int wr = tid >> 5;
    const int wc = (tid & 31) * 2;
#pragma unroll
    for (int i = 0; i < 8; ++i) {
        const int r = i * 8 + wr;
        float v0 = t[wc][r], v1 = t[wc + 1][r];
        __nv_bfloat16 h0, l0, h1, l1;
        split_hilo(v0, h0, l0);
        split_hilo(v1, h1, l1);
        const size_t o = (size_t)(hw0 + r) * CH + c0 + wc;
        *reinterpret_cast<__nv_bfloat162*>(&H[o]) = __nv_bfloat162(h0, h1);
        *reinterpret_cast<__nv_bfloat162*>(&L[o]) = __nv_bfloat162(l0, l1);
    }
}

// ---------------- kernel 2: qT/kT = xT @ wn^T (mma), out [hw][c] hi/lo ----------------
__global__ __launch_bounds__(256) void k_qk_mma(const float* __restrict__ bq,
                                                const float* __restrict__ bk)
{
    __shared__ __align__(1024) MmaSmem sm;
    const uint32_t sb0 = smem_u32(&sm);

    const int which = blockIdx.z >> 2;
    const int batch = blockIdx.z & 3;
    const size_t xoff = (size_t)batch * HWN * CH;
    const __nv_bfloat16* Xh = xT_ptr(which, 0) + xoff;
    const __nv_bfloat16* Xl = xT_ptr(which, 1) + xoff;
    const __nv_bfloat16* Wh = g_wn_hi[which];
    const __nv_bfloat16* Wl = g_wn_lo[which];
    const float* __restrict__ bias = which ? bk : bq;
    __nv_bfloat16* __restrict__ Hi = (which ? g_kT_hi : g_qT_hi) + xoff;
    __nv_bfloat16* __restrict__ Lo = (which ? g_kT_lo : g_qT_lo) + xoff;

    const int m0 = blockIdx.y * 128;   // hw
    const int n0 = blockIdx.x * 128;   // co

    float acc[2][8][4] = {};
    gemm_hilo(sb0, Xh, Xl, CH, m0, Wh, Wl, CH, n0, CH, acc);

    const int lane = threadIdx.x & 31;
    const int w = threadIdx.x >> 5;
    const int wm = w & 3, wn = w >> 2;
    const int gm_base = m0 + wm * 32 + (lane >> 2);
    const int gn_base = n0 + wn * 64 + (lane & 3) * 2;
#pragma unroll
    for (int mt = 0; mt < 2; ++mt) {
#pragma unroll
        for (int nt = 0; nt < 8; ++nt) {
            const int gn = gn_base + nt * 8;
            const float b0 = bias[gn], b1 = bias[gn + 1];
#pragma unroll
            for (int half = 0; half < 2; ++half) {
                const int gm = gm_base + mt * 16 + half * 8;
                float v0 = acc[mt][nt][half * 2 + 0] + b0;
                float v1 = acc[mt][nt][half * 2 + 1] + b1;
                __nv_bfloat16 h0, l0, h1, l1;
                split_hilo(v0, h0, l0);
                split_hilo(v1, h1, l1);
                const size_t o = (size_t)gm * CH + gn;
                *reinterpret_cast<__nv_bfloat162*>(&Hi[o]) = __nv_bfloat162(h0, h1);
                *reinterpret_cast<__nv_bfloat162*>(&Lo[o]) = __nv_bfloat162(l0, l1);
            }
        }
    }
}

// ---------------- kernel 3: sim = qT @ kT^T (mma.sync), 3 CTAs/SM target ----------------
__global__ __launch_bounds__(256, 3) void k_sim_mma()
{
    __shared__ __align__(1024) MmaSmem sm;
    const uint32_t sb0 = smem_u32(&sm);

    const int batch = blockIdx.z;
    const int m0 = blockIdx.y * 128;
    const int n0 = blockIdx.x * 128;
    const size_t boff = (size_t)batch * HWN * CH;

    float acc[2][8][4] = {};
    gemm_hilo(sb0, g_qT_hi + boff, g_qT_lo + boff, CH, m0,
              g_kT_hi + boff, g_kT_lo + boff, CH, n0, CH, acc);

    float* __restrict__ S = g_sim + (size_t)batch * HWN * HWN;
    const int lane = threadIdx.x & 31;
    const int w = threadIdx.x >> 5;
    const int wm = w & 3, wn = w >> 2;
    const int gm_base = m0 + wm * 32 + (lane >> 2);
    const int gn_base = n0 + wn * 64 + (lane & 3) * 2;
#pragma unroll
    for (int mt = 0; mt < 2; ++mt) {
#pragma unroll
        for (int nt = 0; nt < 8; ++nt) {
            const int gm = gm_base + mt * 16;
            const int gn = gn_base + nt * 8;
            float2 p0 = {acc[mt][nt][0], acc[mt][nt][1]};
            float2 p1 = {acc[mt][nt][2], acc[mt][nt][3]};
            *reinterpret_cast<float2*>(&S[(size_t)gm * HWN + gn]) = p0;
            *reinterpret_cast<float2*>(&S[(size_t)(gm + 8) * HWN + gn]) = p1;
        }
    }
}

// ---------------- kernel 4: v = wn @ aT^T (mma), out [c][hw] hi/lo ----------------
__global__ __launch_bounds__(256) void k_v_mma(const float* __restrict__ bv)
{
    __shared__ __align__(1024) MmaSmem sm;
    const uint32_t sb0 = smem_u32(&sm);

    const int batch = blockIdx.z;
    const size_t xoff = (size_t)batch * HWN * CH;
    const size_t voff = (size_t)batch * CH * HWN;

    const int m0 = blockIdx.y * 128;   // c
    const int n0 = blockIdx.x * 128;   // hw

    float acc[2][8][4] = {};
    gemm_hilo(sb0, g_wn_hi[2], g_wn_lo[2], CH, m0,
              xT_ptr(0, 0) + xoff, xT_ptr(0, 1) + xoff, CH, n0, CH, acc);

    const int lane = threadIdx.x & 31;
    const int w = threadIdx.x >> 5;
    const int wm = w & 3, wn = w >> 2;
    const int gm_base = m0 + wm * 32 + (lane >> 2);
    const int gn_base = n0 + wn * 64 + (lane & 3) * 2;
#pragma unroll
    for (int mt = 0; mt < 2; ++mt) {
#pragma unroll
        for (int nt = 0; nt < 8; ++nt) {
            const int gn = gn_base + nt * 8;
#pragma unroll
            for (int half = 0; half < 2; ++half) {
                const int gm = gm_base + mt * 16 + half * 8;
                const float bb = bv[gm];
                float v0 = acc[mt][nt][half * 2 + 0] + bb;
                float v1 = acc[mt][nt][half * 2 + 1] + bb;
                __nv_bfloat16 h0, l0, h1, l1;
                split_hilo(v0, h0, l0);
                split_hilo(v1, h1, l1);
                const size_t o = voff + (size_t)gm * HWN + gn;
                *reinterpret_cast<__nv_bfloat162*>(&g_v_hi[o]) = __nv_bfloat162(h0, h1);
                *reinterpret_cast<__nv_bfloat162*>(&g_v_lo[o]) = __nv_bfloat162(l0, l1);
            }
        }
    }
}

// ---------------- kernel 5: masked softmax -> att bf16 hi/lo ----------------
__global__ __launch_bounds__(256) void k_softmax(const float* __restrict__ cIn)
{
    const int i = blockIdx.x;
    const int batch = blockIdx.y;
    const float* __restrict__ row = g_sim + ((size_t)batch * HWN + i) * HWN;
    __nv_bfloat16* __restrict__ Hi = g_att_hi + ((size_t)batch * HWN + i) * HWN;
    __nv_bfloat16* __restrict__ Lo = g_att_lo + ((size_t)batch * HWN + i) * HWN;

    const int h = i >> 6, w = i & 63;
    const float m = cIn[batch * MASKN + (h >> 1) * 32 + (w >> 1)];

    const int tid = threadIdx.x;
    float x[16];
    float vmax = -CUDART_INF_F;
#pragma unroll
    for (int p = 0; p < 4; ++p) {
        float4 v = *reinterpret_cast<const float4*>(&row[(p * 256 + tid) * 4]);
        x[p * 4 + 0] = m * v.x; x[p * 4 + 1] = m * v.y;
        x[p * 4 + 2] = m * v.z; x[p * 4 + 3] = m * v.w;
#pragma unroll
        for (int q = 0; q < 4; ++q) vmax = fmaxf(vmax, x[p * 4 + q]);
    }

    __shared__ float redm[8], reds[8], sh_max, sh_sum;
#pragma unroll
    for (int off = 16; off; off >>= 1) vmax = fmaxf(vmax, __shfl_xor_sync(0xFFFFFFFFu, vmax, off));
    if ((tid & 31) == 0) redm[tid >> 5] = vmax;
    __syncthreads();
    if (tid == 0) {
        float v = redm[0];
#pragma unroll
        for (int k = 1; k < 8; ++k) v = fmaxf(v, redm[k]);
        sh_max = v;
    }
    __syncthreads();
    const float M = sh_max;

    float total = 0.f;
#pragma unroll
    for (int q = 0; q < 16; ++q) {
        float e = __expf(x[q] - M);
        x[q] = e;
        total += e;
    }
#pragma unroll
    for (int off = 16; off; off >>= 1) total += __shfl_xor_sync(0xFFFFFFFFu, total, off);
    if ((tid & 31) == 0) reds[tid >> 5] = total;
    __syncthreads();
    if (tid == 0) {
        float v = 0.f;
#pragma unroll
        for (int k = 0; k < 8; ++k) v += reds[k];
        sh_sum = v;
    }
    __syncthreads();
    const float inv = 1.0f / sh_sum;

#pragma unroll
    for (int p = 0; p < 4; ++p) {
        const int idx = (p * 256 + tid) * 4;
#pragma unroll
        for (int q = 0; q < 4; q += 2) {
            float v0 = x[p * 4 + q] * inv;
            float v1 = x[p * 4 + q + 1] * inv;
            __nv_bfloat16 h0, l0, h1, l1;
            split_hilo(v0, h0, l0);
            split_hilo(v1, h1, l1);
            *reinterpret_cast<__nv_bfloat162*>(&Hi[idx + q]) = __nv_bfloat162(h0, h1);
            *reinterpret_cast<__nv_bfloat162*>(&Lo[idx + q]) = __nv_bfloat162(l0, l1);
        }
    }
}

// ---------------- kernel 6: out = v @ att^T (mma.sync), fused blend, 3 CTAs/SM ----------------
__global__ __launch_bounds__(256, 3) void k_pv_mma(const float* __restrict__ aIn,
                                                   const float* __restrict__ cIn,
                                                   const float* __restrict__ gammaPtr,
                                                   float* __restrict__ out)
{
    __shared__ __align__(1024) MmaSmem sm;
    const uint32_t sb0 = smem_u32(&sm);

    const int batch = blockIdx.z;
    const int m0 = blockIdx.y * 128;   // channel
    const int n0 = blockIdx.x * 128;   // position i
    const size_t voff = (size_t)batch * CH * HWN;
    const size_t aoff = (size_t)batch * HWN * HWN;

    float acc[2][8][4] = {};
    gemm_hilo(sb0, g_v_hi + voff, g_v_lo + voff, HWN, m0,
              g_att_hi + aoff, g_att_lo + aoff, HWN, n0, HWN, acc);

    const float gamma = gammaPtr[0];
    const int lane = threadIdx.x & 31;
    const int w = threadIdx.x >> 5;
    const int wm = w & 3, wn = w >> 2;
    const int gm_base = m0 + wm * 32 + (lane >> 2);
    const int gn_base = n0 + wn * 64 + (lane & 3) * 2;

#pragma unroll
    for (int mt = 0; mt < 2; ++mt) {
#pragma unroll
        for (int nt = 0; nt < 8; ++nt) {
            const int gi = gn_base + nt * 8;
            const int hh = gi >> 6, ww = gi & 63;
            const float cr = cIn[batch * MASKN + (hh >> 1) * 32 + (ww >> 1)];
            const float gb = gamma * (1.0f - cr);
#pragma unroll
            for (int half = 0; half < 2; ++half) {
                const int gm = gm_base + mt * 16 + half * 8;
                const size_t base = ((size_t)batch * CH + gm) * HWN + gi;
                float2 av = *reinterpret_cast<const float2*>(&aIn[base]);
                float2 o;
                o.x = av.x * cr + gb * acc[mt][nt][half * 2 + 0];
                o.y = av.y * cr + gb * acc[mt][nt][half * 2 + 1];
                *reinterpret_cast<float2*>(&out[base]) = o;
            }
        }
    }
}

// ---------------- launch ----------------
extern "C" void kernel_launch(void* const* d_in, const int* in_sizes, int n_in,
                              void* d_out, int out_size)
{
    const float* a     = (const float*)d_in[0];
    const float* b     = (const float*)d_in[1];
    const float* cmask = (const float*)d_in[2];
    const float* wq    = (const float*)d_in[3];
    const float* bq    = (const float*)d_in[4];
    const float* gq    = (const float*)d_in[5];
    const float* wk    = (const float*)d_in[6];
    const float* bk    = (const float*)d_in[7];
    const float* gk    = (const float*)d_in[8];
    const float* wv    = (const float*)d_in[9];
    const float* bv    = (const float*)d_in[10];
    const float* gv    = (const float*)d_in[11];
    const float* gamma = (const float*)d_in[12];
    float* out = (float*)d_out;

    k_ws<<<dim3(CH, 3), 256>>>(wq, gq, wk, gk, wv, gv);          // launch 1

    dim3 gsp(HWN / 64, CH / 64, 8);
    k_split<<<gsp, 256>>>(a, b);                                  // launch 2

    dim3 gqk(CH / 128, HWN / 128, 8);
    k_qk_mma<<<gqk, 256>>>(bq, bk);                               // launch 3

    dim3 gsim(HWN / 128, HWN / 128, BATCH);
    k_sim_mma<<<gsim, 256>>>();                                   // launch 4 (ncu capture slot)

    dim3 gvv(HWN / 128, CH / 128, BATCH);
    k_v_mma<<<gvv, 256>>>(bv);                                    // launch 5 (before softmax overwrites aT)

    k_softmax<<<dim3(HWN, BATCH), 256>>>(cmask);                  // launch 6

    dim3 gpv(HWN / 128, CH / 128, BATCH);
    k_pv_mma<<<gpv, 256>>>(a, cmask, gamma, out);                 // launch 7
}